// round 3
// baseline (speedup 1.0000x reference)
#include <cuda_runtime.h>
#include <math.h>

#define SEQ    2048
#define HID    4096
#define NHEADS 32
#define NKV    8
#define HD     128
#define QD     (NHEADS*HD)    // 4096
#define KVD    (NKV*HD)       // 1024

// Scratch (allocation-free rule: __device__ globals)
__device__ float g_q[SEQ*QD];
__device__ float g_k[SEQ*KVD];
__device__ float g_v[SEQ*KVD];
__device__ float g_attn[SEQ*QD];

// ---------------------------------------------------------------------------
// SGEMM: C[M,N] = A[M,K] @ B[K,N] + bias   (BM=BN=128, BK=16, 8x8 micro-tile)
// ---------------------------------------------------------------------------
#define BM 128
#define BN 128
#define BK 16

__global__ __launch_bounds__(256)
void sgemm_bias(const float* __restrict__ A, const float* __restrict__ B,
                const float* __restrict__ bias, float* __restrict__ C,
                int M, int N, int K)
{
    __shared__ float As[BK][BM];   // A stored transposed: As[k][m]
    __shared__ float Bs[BK][BN];

    const int tid = threadIdx.x;
    const int tx  = tid & 15;
    const int ty  = tid >> 4;
    const int bm  = blockIdx.y * BM;
    const int bn  = blockIdx.x * BN;

    float acc[8][8];
#pragma unroll
    for (int i = 0; i < 8; i++)
#pragma unroll
        for (int j = 0; j < 8; j++) acc[i][j] = 0.f;

    for (int k0 = 0; k0 < K; k0 += BK) {
        // Load A tile (128x16) transposed into As + B tile (16x128)
#pragma unroll
        for (int it = 0; it < 2; it++) {
            int idx = tid + it*256;            // 0..511
            int row = idx >> 2;                // 0..127
            int c4  = (idx & 3) << 2;          // 0,4,8,12
            float4 va = *(const float4*)(A + (size_t)(bm+row)*K + k0 + c4);
            As[c4+0][row] = va.x;
            As[c4+1][row] = va.y;
            As[c4+2][row] = va.z;
            As[c4+3][row] = va.w;

            int brow = idx >> 5;               // 0..15
            int bc4  = (idx & 31) << 2;        // 0..124
            *(float4*)&Bs[brow][bc4] = *(const float4*)(B + (size_t)(k0+brow)*N + bn + bc4);
        }
        __syncthreads();

#pragma unroll
        for (int kk = 0; kk < BK; kk++) {
            float a[8], b[8];
#pragma unroll
            for (int i = 0; i < 8; i++) a[i] = As[kk][ty + 16*i];
#pragma unroll
            for (int j = 0; j < 8; j++) b[j] = Bs[kk][tx + 16*j];
#pragma unroll
            for (int i = 0; i < 8; i++)
#pragma unroll
                for (int j = 0; j < 8; j++) acc[i][j] += a[i]*b[j];
        }
        __syncthreads();
    }

#pragma unroll
    for (int j = 0; j < 8; j++) {
        float bj = bias[bn + tx + 16*j];
#pragma unroll
        for (int i = 0; i < 8; i++) {
            C[(size_t)(bm + ty + 16*i)*N + bn + tx + 16*j] = acc[i][j] + bj;
        }
    }
}

// ---------------------------------------------------------------------------
// RoPE (GPT-NeoX rotate_half), in place on q and k.
// grid = (SEQ, NHEADS+NKV), block = 64 threads (one per rotation pair)
// ---------------------------------------------------------------------------
__global__ void rope_kernel(float* __restrict__ q, float* __restrict__ k,
                            const int* __restrict__ pos_ids)
{
    int s  = blockIdx.x;
    int hh = blockIdx.y;
    int i  = threadIdx.x;               // 0..63
    int pos = pos_ids[s];

    // inv_freq[i] = 10000^(-i/64); match numpy: double math, cast angle to float
    double invf = exp(-(double)i * (log(10000.0) / 64.0));
    float ang = (float)((double)pos * invf);
    float sn, cs;
    sincosf(ang, &sn, &cs);

    float* base = (hh < NHEADS) ? (q + (size_t)s*QD  + hh*HD)
                                : (k + (size_t)s*KVD + (hh-NHEADS)*HD);
    float x = base[i];
    float y = base[i+64];
    base[i]    = x*cs - y*sn;           // t*cos + rotate_half(t)*sin, first half
    base[i+64] = y*cs + x*sn;           // second half
}

// ---------------------------------------------------------------------------
// Causal flash attention, fp32, online softmax.
// Block = (head h, 64-query tile qt). 256 threads.
// smem: Qs[64][129], KVs[64][129] (K then reused for V), Ss[64][65], stats.
// ---------------------------------------------------------------------------
#define ATTN_SMEM ((64*129*2 + 64*65 + 64*3) * 4)

__global__ __launch_bounds__(256)
void attn_kernel(const float* __restrict__ q, const float* __restrict__ k,
                 const float* __restrict__ v, float* __restrict__ o)
{
    extern __shared__ float sm[];
    float* Qs  = sm;                 // 64 x 129
    float* KVs = Qs + 64*129;        // 64 x 129
    float* Ss  = KVs + 64*129;       // 64 x 65
    float* m_s = Ss + 64*65;         // 64
    float* l_s = m_s + 64;           // 64
    float* c_s = l_s + 64;           // 64

    const int tid = threadIdx.x;
    const int tx = tid & 15, ty = tid >> 4;
    const int qt  = blockIdx.x;      // query tile 0..31
    const int h   = blockIdx.y;      // head 0..31
    const int kvh = h >> 2;          // GQA: 4 q-heads share a kv head
    const float scale = 0.08838834764831845f;  // 1/sqrt(128)

    // Load Q tile, pre-scaled
#pragma unroll
    for (int it = 0; it < 8; it++) {
        int idx = tid + it*256;      // float4 index 0..2047
        int row = idx >> 5;
        int c4  = (idx & 31) << 2;
        float4 va = *(const float4*)(q + (size_t)(qt*64+row)*QD + h*HD + c4);
        float* d = Qs + row*129 + c4;
        d[0]=va.x*scale; d[1]=va.y*scale; d[2]=va.z*scale; d[3]=va.w*scale;
    }
    if (tid < 64) { m_s[tid] = -INFINITY; l_s[tid] = 0.f; }

    float o_acc[4][8];
#pragma unroll
    for (int i = 0; i < 4; i++)
#pragma unroll
        for (int j = 0; j < 8; j++) o_acc[i][j] = 0.f;

    __syncthreads();

    for (int kt = 0; kt <= qt; kt++) {
        // Load K tile into KVs
#pragma unroll
        for (int it = 0; it < 8; it++) {
            int idx = tid + it*256;
            int row = idx >> 5;
            int c4  = (idx & 31) << 2;
            float4 va = *(const float4*)(k + (size_t)(kt*64+row)*KVD + kvh*HD + c4);
            float* d = KVs + row*129 + c4;
            d[0]=va.x; d[1]=va.y; d[2]=va.z; d[3]=va.w;
        }
        __syncthreads();

        // S = (Q*scale) @ K^T  (64x64, 4x4 per thread, strided mapping)
        float sacc[4][4];
#pragma unroll
        for (int i = 0; i < 4; i++)
#pragma unroll
            for (int j = 0; j < 4; j++) sacc[i][j] = 0.f;

        for (int kk = 0; kk < 128; kk++) {
            float a[4], b[4];
#pragma unroll
            for (int i = 0; i < 4; i++) a[i] = Qs[(ty+16*i)*129 + kk];
#pragma unroll
            for (int j = 0; j < 4; j++) b[j] = KVs[(tx+16*j)*129 + kk];
#pragma unroll
            for (int i = 0; i < 4; i++)
#pragma unroll
                for (int j = 0; j < 4; j++) sacc[i][j] += a[i]*b[j];
        }

        const bool diag = (kt == qt);
#pragma unroll
        for (int i = 0; i < 4; i++) {
            int r = ty + 16*i;
#pragma unroll
            for (int j = 0; j < 4; j++) {
                int c = tx + 16*j;
                Ss[r*65 + c] = (diag && c > r) ? -1e30f : sacc[i][j];
            }
        }
        __syncthreads();   // all KVs reads + Ss writes done

        // Load V tile over KVs (independent of Ss)
#pragma unroll
        for (int it = 0; it < 8; it++) {
            int idx = tid + it*256;
            int row = idx >> 5;
            int c4  = (idx & 31) << 2;
            float4 va = *(const float4*)(v + (size_t)(kt*64+row)*KVD + kvh*HD + c4);
            float* d = KVs + row*129 + c4;
            d[0]=va.x; d[1]=va.y; d[2]=va.z; d[3]=va.w;
        }

        // Online softmax: one thread per row (exclusive row ownership -> no race)
        if (tid < 64) {
            int r = tid;
            float mo = m_s[r];
            float mx = mo;
#pragma unroll 8
            for (int c = 0; c < 64; c++) mx = fmaxf(mx, Ss[r*65 + c]);
            float corr = __expf(mo - mx);   // first tile: exp(-inf)=0
            float sum = 0.f;
#pragma unroll 8
            for (int c = 0; c < 64; c++) {
                float p = __expf(Ss[r*65 + c] - mx);
                Ss[r*65 + c] = p;
                sum += p;
            }
            l_s[r] = l_s[r]*corr + sum;
            m_s[r] = mx;
            c_s[r] = corr;
        }
        __syncthreads();   // V in smem + P + stats all visible

        // O = O*corr + P @ V   (64x128, 4x8 per thread)
#pragma unroll
        for (int i = 0; i < 4; i++) {
            float cr = c_s[ty + 16*i];
#pragma unroll
            for (int j = 0; j < 8; j++) o_acc[i][j] *= cr;
        }
        for (int kk = 0; kk < 64; kk++) {
            float p[4], b[8];
#pragma unroll
            for (int i = 0; i < 4; i++) p[i] = Ss[(ty+16*i)*65 + kk];
#pragma unroll
            for (int j = 0; j < 8; j++) b[j] = KVs[kk*129 + tx + 16*j];
#pragma unroll
            for (int i = 0; i < 4; i++)
#pragma unroll
                for (int j = 0; j < 8; j++) o_acc[i][j] += p[i]*b[j];
        }
        __syncthreads();   // before next tile overwrites KVs/Ss
    }

    // Normalize and store
#pragma unroll
    for (int i = 0; i < 4; i++) {
        int r = ty + 16*i;
        float inv_l = 1.f / l_s[r];
#pragma unroll
        for (int j = 0; j < 8; j++) {
            o[(size_t)(qt*64+r)*QD + h*HD + tx + 16*j] = o_acc[i][j] * inv_l;
        }
    }
}

// ---------------------------------------------------------------------------
// Launch
// ---------------------------------------------------------------------------
extern "C" void kernel_launch(void* const* d_in, const int* in_sizes, int n_in,
                              void* d_out, int out_size)
{
    const float* hidden = (const float*)d_in[0];
    // d_in[1] = attention_mask: all-True by construction; causality applied exactly.
    const int*   pos_ids = (const int*)d_in[2];
    const float* Wq = (const float*)d_in[3];
    const float* bq = (const float*)d_in[4];
    const float* Wk = (const float*)d_in[5];
    const float* bk = (const float*)d_in[6];
    const float* Wv = (const float*)d_in[7];
    const float* bv = (const float*)d_in[8];
    const float* Wo = (const float*)d_in[9];
    const float* bo = (const float*)d_in[10];
    float* out = (float*)d_out;

    float *pq = nullptr, *pk = nullptr, *pv = nullptr, *pa = nullptr;
    cudaGetSymbolAddress((void**)&pq, g_q);
    cudaGetSymbolAddress((void**)&pk, g_k);
    cudaGetSymbolAddress((void**)&pv, g_v);
    cudaGetSymbolAddress((void**)&pa, g_attn);

    cudaFuncSetAttribute(attn_kernel, cudaFuncAttributeMaxDynamicSharedMemorySize, ATTN_SMEM);

    dim3 blk(256);

    // QKV projections
    sgemm_bias<<<dim3(QD /BN, SEQ/BM), blk>>>(hidden, Wq, bq, pq, SEQ, QD,  HID);
    sgemm_bias<<<dim3(KVD/BN, SEQ/BM), blk>>>(hidden, Wk, bk, pk, SEQ, KVD, HID);
    sgemm_bias<<<dim3(KVD/BN, SEQ/BM), blk>>>(hidden, Wv, bv, pv, SEQ, KVD, HID);

    // RoPE on q and k
    rope_kernel<<<dim3(SEQ, NHEADS+NKV), 64>>>(pq, pk, pos_ids);

    // Causal flash attention
    attn_kernel<<<dim3(SEQ/64, NHEADS), blk, ATTN_SMEM>>>(pq, pk, pv, pa);

    // Output projection
    sgemm_bias<<<dim3(HID/BN, SEQ/BM), blk>>>(pa, Wo, bo, out, SEQ, HID, QD);
}

// round 4
// speedup vs baseline: 2.0817x; 2.0817x over previous
#include <cuda_runtime.h>
#include <math.h>
#include <stdint.h>

#define SEQ    2048
#define HID    4096
#define NHEADS 32
#define NKV    8
#define HD     128
#define QD     (NHEADS*HD)    // 4096
#define KVD    (NKV*HD)       // 1024

// Scratch (allocation-free rule: __device__ globals)
__device__ float g_q[SEQ*QD];
__device__ float g_k[SEQ*KVD];
__device__ float g_v[SEQ*KVD];
__device__ float g_attn[SEQ*QD];

// ---------------------------------------------------------------------------
// tf32 helpers
// ---------------------------------------------------------------------------
__device__ __forceinline__ uint32_t f2t(float x) {
    uint32_t r;
    asm("cvt.rna.tf32.f32 %0, %1;" : "=r"(r) : "f"(x));
    return r;
}

__device__ __forceinline__ void mma8(float* c, const uint32_t* a, const uint32_t* b) {
    asm volatile("mma.sync.aligned.m16n8k8.row.col.f32.tf32.tf32.f32 "
                 "{%0,%1,%2,%3}, {%4,%5,%6,%7}, {%8,%9}, {%0,%1,%2,%3};"
                 : "+f"(c[0]), "+f"(c[1]), "+f"(c[2]), "+f"(c[3])
                 : "r"(a[0]), "r"(a[1]), "r"(a[2]), "r"(a[3]),
                   "r"(b[0]), "r"(b[1]));
}

// ---------------------------------------------------------------------------
// tf32 tensor-core GEMM: C[M,N] = A[M,K] @ B[K,N] + bias
// Block tile 128x128x32, 8 warps (4m x 2n), warp tile 32x64 (m16n8k8 tiles).
// smem layout As[k][m], Bs[k][n], stride 136 (==8 mod 32 -> conflict-free
// fragment LDS: bank = 8*tig + g, all distinct). Double-buffered via regs.
// ---------------------------------------------------------------------------
#define GBM 128
#define GBN 128
#define GBK 32
#define GSTR 136
#define GEMM_SMEM (4 * GBK * GSTR * 4)   // 2 bufs x (A+B) tiles, u32

__global__ __launch_bounds__(256)
void gemm_tf32(const float* __restrict__ A, const float* __restrict__ B,
               const float* __restrict__ bias, float* __restrict__ C,
               int M, int N, int K)
{
    extern __shared__ uint32_t smem[];
    uint32_t* Asm = smem;                   // [2][GBK][GSTR]
    uint32_t* Bsm = smem + 2 * GBK * GSTR;  // [2][GBK][GSTR]

    const int tid  = threadIdx.x;
    const int lane = tid & 31;
    const int warp = tid >> 5;
    const int g    = lane >> 2;     // groupID
    const int tig  = lane & 3;      // thread-in-group
    const int wm0  = (warp >> 1) * 32;
    const int wn0  = (warp & 1) * 64;
    const int bm   = blockIdx.y * GBM;
    const int bn   = blockIdx.x * GBN;

    // global load mapping
    const int am  = tid & 127;          // A row in tile (warp: 32 consecutive)
    const int akb = (tid >> 7) * 16;    // A k base (0 or 16)
    const int bk  = tid >> 3;           // B k row (0..31)
    const int bnb = (tid & 7) * 4;      // B n base; f stride 32

    const float* Ag = A + (size_t)(bm + am) * K + akb;
    const float* Bg = B + (size_t)bk * N + bn + bnb;

    float acc[2][8][4];
#pragma unroll
    for (int mt = 0; mt < 2; mt++)
#pragma unroll
        for (int nt = 0; nt < 8; nt++)
#pragma unroll
            for (int c = 0; c < 4; c++) acc[mt][nt][c] = 0.f;

    float4 ra[4], rb[4];

    // prologue: load tile 0 into regs
#pragma unroll
    for (int f = 0; f < 4; f++) {
        ra[f] = *(const float4*)(Ag + f * 4);
        rb[f] = *(const float4*)(Bg + f * 32);
    }

    const int nTiles = K / GBK;

    // store tile 0 (buf 0)
    {
        uint32_t* as = Asm;
        uint32_t* bs = Bsm;
#pragma unroll
        for (int f = 0; f < 4; f++) {
            int k = akb + f * 4;
            as[(k + 0) * GSTR + am] = f2t(ra[f].x);
            as[(k + 1) * GSTR + am] = f2t(ra[f].y);
            as[(k + 2) * GSTR + am] = f2t(ra[f].z);
            as[(k + 3) * GSTR + am] = f2t(ra[f].w);
            int n = bnb + f * 32;
            bs[bk * GSTR + n + 0] = f2t(rb[f].x);
            bs[bk * GSTR + n + 1] = f2t(rb[f].y);
            bs[bk * GSTR + n + 2] = f2t(rb[f].z);
            bs[bk * GSTR + n + 3] = f2t(rb[f].w);
        }
    }
    __syncthreads();

    for (int t = 0; t < nTiles; t++) {
        // prefetch next tile into regs
        if (t + 1 < nTiles) {
            const float* Ag2 = Ag + (t + 1) * GBK;
            const float* Bg2 = Bg + (size_t)(t + 1) * GBK * N;
#pragma unroll
            for (int f = 0; f < 4; f++) {
                ra[f] = *(const float4*)(Ag2 + f * 4);
                rb[f] = *(const float4*)(Bg2 + f * 32);
            }
        }

        const uint32_t* as = Asm + (t & 1) * GBK * GSTR;
        const uint32_t* bs = Bsm + (t & 1) * GBK * GSTR;

#pragma unroll
        for (int k8 = 0; k8 < 4; k8++) {
            const int k0 = k8 * 8;
            uint32_t afr[2][4], bfr[8][2];
#pragma unroll
            for (int mt = 0; mt < 2; mt++) {
                int m = wm0 + mt * 16 + g;
                afr[mt][0] = as[(k0 + tig) * GSTR + m];
                afr[mt][1] = as[(k0 + tig) * GSTR + m + 8];
                afr[mt][2] = as[(k0 + tig + 4) * GSTR + m];
                afr[mt][3] = as[(k0 + tig + 4) * GSTR + m + 8];
            }
#pragma unroll
            for (int nt = 0; nt < 8; nt++) {
                int n = wn0 + nt * 8 + g;
                bfr[nt][0] = bs[(k0 + tig) * GSTR + n];
                bfr[nt][1] = bs[(k0 + tig + 4) * GSTR + n];
            }
#pragma unroll
            for (int mt = 0; mt < 2; mt++)
#pragma unroll
                for (int nt = 0; nt < 8; nt++)
                    mma8(acc[mt][nt], afr[mt], bfr[nt]);
        }

        __syncthreads();

        if (t + 1 < nTiles) {
            uint32_t* asn = Asm + ((t + 1) & 1) * GBK * GSTR;
            uint32_t* bsn = Bsm + ((t + 1) & 1) * GBK * GSTR;
#pragma unroll
            for (int f = 0; f < 4; f++) {
                int k = akb + f * 4;
                asn[(k + 0) * GSTR + am] = f2t(ra[f].x);
                asn[(k + 1) * GSTR + am] = f2t(ra[f].y);
                asn[(k + 2) * GSTR + am] = f2t(ra[f].z);
                asn[(k + 3) * GSTR + am] = f2t(ra[f].w);
                int n = bnb + f * 32;
                bsn[bk * GSTR + n + 0] = f2t(rb[f].x);
                bsn[bk * GSTR + n + 1] = f2t(rb[f].y);
                bsn[bk * GSTR + n + 2] = f2t(rb[f].z);
                bsn[bk * GSTR + n + 3] = f2t(rb[f].w);
            }
            __syncthreads();
        }
    }

    // epilogue: bias + store (float2 per fragment row-half)
#pragma unroll
    for (int mt = 0; mt < 2; mt++) {
#pragma unroll
        for (int nt = 0; nt < 8; nt++) {
            int row = bm + wm0 + mt * 16 + g;
            int col = bn + wn0 + nt * 8 + tig * 2;
            float b0 = bias[col], b1 = bias[col + 1];
            float2 v0 = make_float2(acc[mt][nt][0] + b0, acc[mt][nt][1] + b1);
            float2 v1 = make_float2(acc[mt][nt][2] + b0, acc[mt][nt][3] + b1);
            *(float2*)(C + (size_t)row * N + col)       = v0;
            *(float2*)(C + (size_t)(row + 8) * N + col) = v1;
        }
    }
}

// ---------------------------------------------------------------------------
// RoPE (GPT-NeoX rotate_half), in place on q and k.
// grid = SEQ, block = 64. Each thread computes sin/cos ONCE, loops all heads.
// ---------------------------------------------------------------------------
__global__ void rope_kernel(float* __restrict__ q, float* __restrict__ k,
                            const int* __restrict__ pos_ids)
{
    int s = blockIdx.x;
    int i = threadIdx.x;                // 0..63
    int pos = pos_ids[s];

    // inv_freq[i] = 10000^(-i/64); match numpy: double math, cast angle to float
    double invf = exp(-(double)i * (log(10000.0) / 64.0));
    float ang = (float)((double)pos * invf);
    float sn, cs;
    sincosf(ang, &sn, &cs);

    float* qb = q + (size_t)s * QD;
#pragma unroll
    for (int h = 0; h < NHEADS; h++) {
        float x = qb[h * HD + i];
        float y = qb[h * HD + i + 64];
        qb[h * HD + i]      = x * cs - y * sn;
        qb[h * HD + i + 64] = y * cs + x * sn;
    }
    float* kb = k + (size_t)s * KVD;
#pragma unroll
    for (int h = 0; h < NKV; h++) {
        float x = kb[h * HD + i];
        float y = kb[h * HD + i + 64];
        kb[h * HD + i]      = x * cs - y * sn;
        kb[h * HD + i + 64] = y * cs + x * sn;
    }
}

// ---------------------------------------------------------------------------
// Causal flash attention, fp32, online softmax (unchanged from R3, passing).
// ---------------------------------------------------------------------------
#define ATTN_SMEM ((64*129*2 + 64*65 + 64*3) * 4)

__global__ __launch_bounds__(256)
void attn_kernel(const float* __restrict__ q, const float* __restrict__ k,
                 const float* __restrict__ v, float* __restrict__ o)
{
    extern __shared__ float sm[];
    float* Qs  = sm;                 // 64 x 129
    float* KVs = Qs + 64*129;        // 64 x 129
    float* Ss  = KVs + 64*129;       // 64 x 65
    float* m_s = Ss + 64*65;         // 64
    float* l_s = m_s + 64;           // 64
    float* c_s = l_s + 64;           // 64

    const int tid = threadIdx.x;
    const int tx = tid & 15, ty = tid >> 4;
    const int qt  = blockIdx.x;      // query tile 0..31
    const int h   = blockIdx.y;      // head 0..31
    const int kvh = h >> 2;          // GQA: 4 q-heads share a kv head
    const float scale = 0.08838834764831845f;  // 1/sqrt(128)

#pragma unroll
    for (int it = 0; it < 8; it++) {
        int idx = tid + it*256;
        int row = idx >> 5;
        int c4  = (idx & 31) << 2;
        float4 va = *(const float4*)(q + (size_t)(qt*64+row)*QD + h*HD + c4);
        float* d = Qs + row*129 + c4;
        d[0]=va.x*scale; d[1]=va.y*scale; d[2]=va.z*scale; d[3]=va.w*scale;
    }
    if (tid < 64) { m_s[tid] = -INFINITY; l_s[tid] = 0.f; }

    float o_acc[4][8];
#pragma unroll
    for (int i = 0; i < 4; i++)
#pragma unroll
        for (int j = 0; j < 8; j++) o_acc[i][j] = 0.f;

    __syncthreads();

    for (int kt = 0; kt <= qt; kt++) {
#pragma unroll
        for (int it = 0; it < 8; it++) {
            int idx = tid + it*256;
            int row = idx >> 5;
            int c4  = (idx & 31) << 2;
            float4 va = *(const float4*)(k + (size_t)(kt*64+row)*KVD + kvh*HD + c4);
            float* d = KVs + row*129 + c4;
            d[0]=va.x; d[1]=va.y; d[2]=va.z; d[3]=va.w;
        }
        __syncthreads();

        float sacc[4][4];
#pragma unroll
        for (int i = 0; i < 4; i++)
#pragma unroll
            for (int j = 0; j < 4; j++) sacc[i][j] = 0.f;

        for (int kk = 0; kk < 128; kk++) {
            float a[4], b[4];
#pragma unroll
            for (int i = 0; i < 4; i++) a[i] = Qs[(ty+16*i)*129 + kk];
#pragma unroll
            for (int j = 0; j < 4; j++) b[j] = KVs[(tx+16*j)*129 + kk];
#pragma unroll
            for (int i = 0; i < 4; i++)
#pragma unroll
                for (int j = 0; j < 4; j++) sacc[i][j] += a[i]*b[j];
        }

        const bool diag = (kt == qt);
#pragma unroll
        for (int i = 0; i < 4; i++) {
            int r = ty + 16*i;
#pragma unroll
            for (int j = 0; j < 4; j++) {
                int c = tx + 16*j;
                Ss[r*65 + c] = (diag && c > r) ? -1e30f : sacc[i][j];
            }
        }
        __syncthreads();

#pragma unroll
        for (int it = 0; it < 8; it++) {
            int idx = tid + it*256;
            int row = idx >> 5;
            int c4  = (idx & 31) << 2;
            float4 va = *(const float4*)(v + (size_t)(kt*64+row)*KVD + kvh*HD + c4);
            float* d = KVs + row*129 + c4;
            d[0]=va.x; d[1]=va.y; d[2]=va.z; d[3]=va.w;
        }

        if (tid < 64) {
            int r = tid;
            float mo = m_s[r];
            float mx = mo;
#pragma unroll 8
            for (int c = 0; c < 64; c++) mx = fmaxf(mx, Ss[r*65 + c]);
            float corr = __expf(mo - mx);
            float sum = 0.f;
#pragma unroll 8
            for (int c = 0; c < 64; c++) {
                float p = __expf(Ss[r*65 + c] - mx);
                Ss[r*65 + c] = p;
                sum += p;
            }
            l_s[r] = l_s[r]*corr + sum;
            m_s[r] = mx;
            c_s[r] = corr;
        }
        __syncthreads();

#pragma unroll
        for (int i = 0; i < 4; i++) {
            float cr = c_s[ty + 16*i];
#pragma unroll
            for (int j = 0; j < 8; j++) o_acc[i][j] *= cr;
        }
        for (int kk = 0; kk < 64; kk++) {
            float p[4], b[8];
#pragma unroll
            for (int i = 0; i < 4; i++) p[i] = Ss[(ty+16*i)*65 + kk];
#pragma unroll
            for (int j = 0; j < 8; j++) b[j] = KVs[kk*129 + tx + 16*j];
#pragma unroll
            for (int i = 0; i < 4; i++)
#pragma unroll
                for (int j = 0; j < 8; j++) o_acc[i][j] += p[i]*b[j];
        }
        __syncthreads();
    }

#pragma unroll
    for (int i = 0; i < 4; i++) {
        int r = ty + 16*i;
        float inv_l = 1.f / l_s[r];
#pragma unroll
        for (int j = 0; j < 8; j++) {
            o[(size_t)(qt*64+r)*QD + h*HD + tx + 16*j] = o_acc[i][j] * inv_l;
        }
    }
}

// ---------------------------------------------------------------------------
// Launch
// ---------------------------------------------------------------------------
extern "C" void kernel_launch(void* const* d_in, const int* in_sizes, int n_in,
                              void* d_out, int out_size)
{
    const float* hidden = (const float*)d_in[0];
    // d_in[1] = attention_mask: all-True by construction; causality applied exactly.
    const int*   pos_ids = (const int*)d_in[2];
    const float* Wq = (const float*)d_in[3];
    const float* bq = (const float*)d_in[4];
    const float* Wk = (const float*)d_in[5];
    const float* bk = (const float*)d_in[6];
    const float* Wv = (const float*)d_in[7];
    const float* bv = (const float*)d_in[8];
    const float* Wo = (const float*)d_in[9];
    const float* bo = (const float*)d_in[10];
    float* out = (float*)d_out;

    float *pq = nullptr, *pk = nullptr, *pv = nullptr, *pa = nullptr;
    cudaGetSymbolAddress((void**)&pq, g_q);
    cudaGetSymbolAddress((void**)&pk, g_k);
    cudaGetSymbolAddress((void**)&pv, g_v);
    cudaGetSymbolAddress((void**)&pa, g_attn);

    cudaFuncSetAttribute(gemm_tf32, cudaFuncAttributeMaxDynamicSharedMemorySize, GEMM_SMEM);
    cudaFuncSetAttribute(attn_kernel, cudaFuncAttributeMaxDynamicSharedMemorySize, ATTN_SMEM);

    dim3 blk(256);

    // QKV projections (tf32 tensor cores)
    gemm_tf32<<<dim3(QD /GBN, SEQ/GBM), blk, GEMM_SMEM>>>(hidden, Wq, bq, pq, SEQ, QD,  HID);
    gemm_tf32<<<dim3(KVD/GBN, SEQ/GBM), blk, GEMM_SMEM>>>(hidden, Wk, bk, pk, SEQ, KVD, HID);
    gemm_tf32<<<dim3(KVD/GBN, SEQ/GBM), blk, GEMM_SMEM>>>(hidden, Wv, bv, pv, SEQ, KVD, HID);

    // RoPE on q and k
    rope_kernel<<<SEQ, 64>>>(pq, pk, pos_ids);

    // Causal flash attention (fp32)
    attn_kernel<<<dim3(SEQ/64, NHEADS), blk, ATTN_SMEM>>>(pq, pk, pv, pa);

    // Output projection (tf32 tensor cores)
    gemm_tf32<<<dim3(HID/GBN, SEQ/GBM), blk, GEMM_SMEM>>>(pa, Wo, bo, out, SEQ, HID, QD);
}